// round 5
// baseline (speedup 1.0000x reference)
#include <cuda_runtime.h>
#include <cstdint>

#define FLEN 1024   // chain length
#define DDIM 1024   // bond dimension
#define HALF 512    // steps per direction
#define NGRP 64     // blocks per direction
#define NBLK (2*NGRP)
#define TPB  256
#define NB   4      // chain-vector ring depth (2 steps of slack)

// Ring-buffered chain vectors + per-block epoch flags (__device__ globals:
// no cudaMalloc anywhere). Flags grow monotonically across graph replays;
// all comparisons are via signed wrap-safe differences against a per-launch
// base (all flags are equal at every launch boundary).
__device__ float4   g_V[NB][DDIM/4];   // forward vector ring
__device__ float4   g_W[NB][DDIM/4];   // backward vector ring
__device__ unsigned g_fl_f[NGRP];
__device__ unsigned g_fl_b[NGRP];

__device__ __forceinline__ unsigned ld_acq(const unsigned* p) {
    unsigned v;
    asm volatile("ld.acquire.gpu.u32 %0, [%1];" : "=r"(v) : "l"(p) : "memory");
    return v;
}
__device__ __forceinline__ void st_rel(unsigned* p, unsigned v) {
    asm volatile("st.release.gpu.u32 [%0], %1;" :: "l"(p), "r"(v) : "memory");
}

__global__ void __launch_bounds__(TPB, 1)
tn_flow_kernel(const int*   __restrict__ x,
               const float* __restrict__ core,
               const float* __restrict__ lb,
               const float* __restrict__ rb,
               float*       __restrict__ out)
{
    __shared__ float sv[DDIM];       // current chain vector (4KB)
    __shared__ float swp[8][4][4];   // fwd cross-warp reduce scratch
    __shared__ float sdata[16];      // this block's 16 outputs
    __shared__ int   sx[HALF];
    __shared__ float sred[8];

    const int tid  = threadIdx.x;
    const int b    = blockIdx.x;
    const int lane = tid & 31;
    const int wid  = tid >> 5;
    const bool fwd = (b < NGRP);
    const int  gb  = fwd ? b : b - NGRP;

    unsigned* flg = fwd ? g_fl_f : g_fl_b;
    float4 (*ring)[DDIM/4] = fwd ? g_V : g_W;

    // Launch-wide flag base: all flags are equal at launch start, and nobody
    // else ever writes OUR flag, so reading it before our first increment
    // yields the common base.
    const unsigned base = ld_acq(&flg[gb]);

    if (fwd) { for (int t = tid; t < HALF; t += TPB) sx[t] = x[t]; }
    else     { for (int t = tid; t < HALF; t += TPB) sx[t] = x[FLEN - 1 - t]; }
    __syncthreads();

    const int seg = tid >> 2;   // producer that owns this thread's v float4

    if (fwd) {
        // ------- forward: v_j <- sum_i v_i M[i][j]; block owns cols [16b,16b+16) -------
        const int c0 = b * 16;
        const int j4 = tid & 3;     // float4 within the 16-col tile
        const int g  = tid >> 2;    // row class: rows g + 64k

        float4 m[16];
        {
            const float4* M4 = reinterpret_cast<const float4*>(
                                   core + ((size_t)sx[0] << 20)) + (c0 >> 2) + j4;
            #pragma unroll
            for (int k = 0; k < 16; ++k) m[k] = __ldcg(&M4[(size_t)(g + 64*k) * 256]);
        }

        for (int t = 0; t < HALF; ++t) {
            // 1. obtain this thread's float4 of the chain vector
            {
                float4 vv;
                if (t == 0) {
                    vv = reinterpret_cast<const float4*>(lb)[tid];
                } else {
                    const unsigned thr = base + (unsigned)t;
                    while ((int)(ld_acq(&g_fl_f[seg]) - thr) < 0) { }
                    vv = __ldcg(&g_V[(t + 3) & 3][tid]);
                }
                reinterpret_cast<float4*>(sv)[tid] = vv;
            }
            __syncthreads();

            // 2. compute (two independent accumulator sets shorten the chain)
            float ax0=0.f, ay0=0.f, az0=0.f, aw0=0.f;
            float ax1=0.f, ay1=0.f, az1=0.f, aw1=0.f;
            #pragma unroll
            for (int k = 0; k < 16; k += 2) {
                const float v0 = sv[g + 64*k];
                const float v1 = sv[g + 64*(k+1)];
                ax0 += v0 * m[k].x;   ay0 += v0 * m[k].y;
                az0 += v0 * m[k].z;   aw0 += v0 * m[k].w;
                ax1 += v1 * m[k+1].x; ay1 += v1 * m[k+1].y;
                az1 += v1 * m[k+1].z; aw1 += v1 * m[k+1].w;
            }
            float ax = ax0 + ax1, ay = ay0 + ay1, az = az0 + az1, aw = aw0 + aw1;

            // 3. prefetch next step's tile (independent of v; overlaps everything)
            if (t + 1 < HALF) {
                const float4* M4 = reinterpret_cast<const float4*>(
                                       core + ((size_t)sx[t+1] << 20)) + (c0 >> 2) + j4;
                #pragma unroll
                for (int k = 0; k < 16; ++k) m[k] = __ldcg(&M4[(size_t)(g + 64*k) * 256]);
            }

            // 4. reduce over row classes: in-warp (g low bits) then cross-warp
            #pragma unroll
            for (int off = 4; off < 32; off <<= 1) {
                ax += __shfl_xor_sync(0xffffffffu, ax, off);
                ay += __shfl_xor_sync(0xffffffffu, ay, off);
                az += __shfl_xor_sync(0xffffffffu, az, off);
                aw += __shfl_xor_sync(0xffffffffu, aw, off);
            }
            if (lane < 4) {
                swp[wid][lane][0] = ax; swp[wid][lane][1] = ay;
                swp[wid][lane][2] = az; swp[wid][lane][3] = aw;
            }
            __syncthreads();
            if (tid < 16) {
                float s = 0.f;
                #pragma unroll
                for (int w = 0; w < 8; ++w) s += swp[w][tid >> 2][tid & 3];
                sdata[tid] = s;
            }
            __syncthreads();

            // 5. write-safety (ring slack: all producers done with step t-3's
            //    buffer, i.e. flags >= base+t-2), then publish + release flag
            if (wid == 0) {
                const unsigned thr2 = base + (unsigned)t - (NB - 2);
                unsigned ok;
                do {
                    const unsigned f0 = ld_acq(&g_fl_f[lane]);
                    const unsigned f1 = ld_acq(&g_fl_f[lane + 32]);
                    ok = ((int)(f0 - thr2) >= 0) && ((int)(f1 - thr2) >= 0);
                } while (!__all_sync(0xffffffffu, ok));
                if (lane == 0) {
                    float4* dst = &g_V[t & 3][c0 >> 2];
                    const float4* sd4 = reinterpret_cast<const float4*>(sdata);
                    __stcg(&dst[0], sd4[0]); __stcg(&dst[1], sd4[1]);
                    __stcg(&dst[2], sd4[2]); __stcg(&dst[3], sd4[3]);
                    st_rel(&g_fl_f[b], base + (unsigned)t + 1u);
                }
            }
        }
    } else {
        // ------- backward: w_i <- sum_j M[i][j] w_j; block owns rows [16gb,16gb+16) -------
        const int r0    = gb * 16;
        const int chunk = tid & 15;      // float4 chunk within the row
        const int row   = r0 + (tid >> 4);

        float4 m[16];
        {
            const float4* M4 = reinterpret_cast<const float4*>(
                                   core + ((size_t)sx[0] << 20))
                               + (size_t)row * 256 + chunk;
            #pragma unroll
            for (int k = 0; k < 16; ++k) m[k] = __ldcg(&M4[16 * k]);
        }

        for (int t = 0; t < HALF; ++t) {
            {
                float4 vv;
                if (t == 0) {
                    vv = reinterpret_cast<const float4*>(rb)[tid];
                } else {
                    const unsigned thr = base + (unsigned)t;
                    while ((int)(ld_acq(&g_fl_b[seg]) - thr) < 0) { }
                    vv = __ldcg(&g_W[(t + 3) & 3][tid]);
                }
                reinterpret_cast<float4*>(sv)[tid] = vv;
            }
            __syncthreads();

            float a0=0.f, a1=0.f, a2=0.f, a3=0.f;
            const float4* sw4 = reinterpret_cast<const float4*>(sv);
            #pragma unroll
            for (int k = 0; k < 16; ++k) {
                const float4 wv = sw4[chunk + 16*k];
                a0 += m[k].x * wv.x; a1 += m[k].y * wv.y;
                a2 += m[k].z * wv.z; a3 += m[k].w * wv.w;
            }
            float acc = (a0 + a1) + (a2 + a3);

            if (t + 1 < HALF) {
                const float4* M4 = reinterpret_cast<const float4*>(
                                       core + ((size_t)sx[t+1] << 20))
                                   + (size_t)row * 256 + chunk;
                #pragma unroll
                for (int k = 0; k < 16; ++k) m[k] = __ldcg(&M4[16 * k]);
            }

            // reduce over chunk (lane bits 0..3)
            #pragma unroll
            for (int off = 1; off < 16; off <<= 1)
                acc += __shfl_xor_sync(0xffffffffu, acc, off);
            if (chunk == 0) sdata[tid >> 4] = acc;
            __syncthreads();

            if (wid == 0) {
                const unsigned thr2 = base + (unsigned)t - (NB - 2);
                unsigned ok;
                do {
                    const unsigned f0 = ld_acq(&g_fl_b[lane]);
                    const unsigned f1 = ld_acq(&g_fl_b[lane + 32]);
                    ok = ((int)(f0 - thr2) >= 0) && ((int)(f1 - thr2) >= 0);
                } while (!__all_sync(0xffffffffu, ok));
                if (lane == 0) {
                    float4* dst = &g_W[t & 3][r0 >> 2];
                    const float4* sd4 = reinterpret_cast<const float4*>(sdata);
                    __stcg(&dst[0], sd4[0]); __stcg(&dst[1], sd4[1]);
                    __stcg(&dst[2], sd4[2]); __stcg(&dst[3], sd4[3]);
                    st_rel(&g_fl_b[gb], base + (unsigned)t + 1u);
                }
            }
        }
    }

    // ------- final combine: block 0 waits for both chains, dots v·w -------
    if (b == 0) {
        const unsigned thrF = base + (unsigned)HALF;
        if (wid == 0) {
            unsigned ok;
            do {
                const unsigned f0 = ld_acq(&g_fl_f[lane]);
                const unsigned f1 = ld_acq(&g_fl_f[lane + 32]);
                const unsigned h0 = ld_acq(&g_fl_b[lane]);
                const unsigned h1 = ld_acq(&g_fl_b[lane + 32]);
                ok = ((int)(f0 - thrF) >= 0) && ((int)(f1 - thrF) >= 0) &&
                     ((int)(h0 - thrF) >= 0) && ((int)(h1 - thrF) >= 0);
            } while (!__all_sync(0xffffffffu, ok));
        }
        __syncthreads();

        const float4 vv = __ldcg(&g_V[(HALF - 1) & 3][tid]);
        const float4 ww = __ldcg(&g_W[(HALF - 1) & 3][tid]);
        float part = vv.x*ww.x + vv.y*ww.y + vv.z*ww.z + vv.w*ww.w;
        #pragma unroll
        for (int off = 16; off > 0; off >>= 1)
            part += __shfl_xor_sync(0xffffffffu, part, off);
        if (lane == 0) sred[wid] = part;
        __syncthreads();
        if (tid == 0) {
            float s = 0.f;
            #pragma unroll
            for (int w = 0; w < 8; ++w) s += sred[w];
            out[0] = s;
        }
    }
}

extern "C" void kernel_launch(void* const* d_in, const int* in_sizes, int n_in,
                              void* d_out, int out_size) {
    const int*   x    = (const int*)  d_in[0];  // int32[1024]
    const float* core = (const float*)d_in[1];  // f32[32,1024,1024]
    const float* lb   = (const float*)d_in[2];  // f32[1024]
    const float* rb   = (const float*)d_in[3];  // f32[1024]
    float*       out  = (float*)d_out;

    tn_flow_kernel<<<NBLK, TPB>>>(x, core, lb, rb, out);
}

// round 6
// speedup vs baseline: 3.5201x; 3.5201x over previous
#include <cuda_runtime.h>
#include <cstdint>

#define FLEN 1024   // chain length
#define DDIM 1024   // bond dimension
#define HALF 512    // steps per direction
#define NGRP 64     // blocks per direction
#define NBLK (2*NGRP)
#define TPB  256

// Double-buffered chain vectors + per-block epoch flags (__device__ globals:
// no cudaMalloc anywhere). Flags grow monotonically across graph replays; at
// every launch boundary ALL flags are equal (each launch adds exactly HALF
// to every flag), so "own flag before first increment" is a valid common base.
__device__ float4 g_V[2][DDIM/4];   // forward vector ring
__device__ float4 g_W[2][DDIM/4];   // backward vector ring
__device__ uint4  g_flag_f[NGRP];   // .x = epoch, padded to 16B
__device__ uint4  g_flag_b[NGRP];

__device__ __forceinline__ unsigned ld_acq(const unsigned* p) {
    unsigned v;
    asm volatile("ld.acquire.gpu.u32 %0, [%1];" : "=r"(v) : "l"(p) : "memory");
    return v;
}
__device__ __forceinline__ void st_rel(unsigned* p, unsigned v) {
    asm volatile("st.release.gpu.u32 [%0], %1;" :: "l"(p), "r"(v) : "memory");
}

// One warp polls all 64 flags of `fl` until every epoch >= thr. Coalesced:
// 2 loads per lane. Everyone else must be parked at __syncthreads.
__device__ __forceinline__ void warp_wait_all(const uint4* fl, unsigned thr) {
    const int lane = threadIdx.x & 31;
    unsigned ok;
    do {
        const unsigned f0 = ld_acq(&fl[lane].x);
        const unsigned f1 = ld_acq(&fl[lane + 32].x);
        ok = ((int)(f0 - thr) >= 0) && ((int)(f1 - thr) >= 0);
    } while (!__all_sync(0xffffffffu, ok));
}

__global__ void __launch_bounds__(TPB, 1)
tn_flag_kernel(const int*   __restrict__ x,
               const float* __restrict__ core,
               const float* __restrict__ lb,
               const float* __restrict__ rb,
               float*       __restrict__ out)
{
    __shared__ float sv[DDIM];       // current chain vector (4KB)
    __shared__ float swp[8][4][4];   // fwd cross-warp reduce scratch
    __shared__ float sdata[16];      // this block's 16 outputs
    __shared__ int   sx[HALF];
    __shared__ float sred[8];

    const int tid  = threadIdx.x;
    const int b    = blockIdx.x;
    const int lane = tid & 31;
    const int wid  = tid >> 5;
    const bool fwd = (b < NGRP);
    const int  gb  = fwd ? b : b - NGRP;

    uint4* flg = fwd ? g_flag_f : g_flag_b;

    // Common launch base: own flag before our first increment (all flags are
    // equal at every launch boundary; nobody else writes our flag).
    const unsigned base = ld_acq(&flg[gb].x);

    if (fwd) { for (int t = tid; t < HALF; t += TPB) sx[t] = x[t]; }
    else     { for (int t = tid; t < HALF; t += TPB) sx[t] = x[FLEN - 1 - t]; }
    __syncthreads();

    if (fwd) {
        // ------- forward: v_j <- sum_i v_i M[i][j]; block owns cols [16b,16b+16) -------
        const int c0 = b * 16;
        const int j4 = tid & 3;     // float4 within the 16-col tile
        const int g  = tid >> 2;    // row class: rows g + 64k

        float4 m[16];
        {   // prefetch step 0
            const float4* M4 = reinterpret_cast<const float4*>(
                                   core + ((size_t)sx[0] << 20)) + (c0 >> 2) + j4;
            #pragma unroll
            for (int k = 0; k < 16; ++k) m[k] = __ldcg(&M4[(size_t)(g + 64*k) * 256]);
        }

        for (int t = 0; t < HALF; ++t) {
            // 1. wait for all producers of step t-1, then fetch chain vector
            if (t > 0) {
                if (wid == 0) warp_wait_all(g_flag_f, base + (unsigned)t);
                __syncthreads();
                reinterpret_cast<float4*>(sv)[tid] =
                    __ldcg(&g_V[(t + 1) & 1][tid]);
            } else {
                reinterpret_cast<float4*>(sv)[tid] =
                    reinterpret_cast<const float4*>(lb)[tid];
            }
            __syncthreads();

            // 2. compute (two independent accumulator sets)
            float ax0=0.f, ay0=0.f, az0=0.f, aw0=0.f;
            float ax1=0.f, ay1=0.f, az1=0.f, aw1=0.f;
            #pragma unroll
            for (int k = 0; k < 16; k += 2) {
                const float v0 = sv[g + 64*k];
                const float v1 = sv[g + 64*(k+1)];
                ax0 += v0 * m[k].x;   ay0 += v0 * m[k].y;
                az0 += v0 * m[k].z;   aw0 += v0 * m[k].w;
                ax1 += v1 * m[k+1].x; ay1 += v1 * m[k+1].y;
                az1 += v1 * m[k+1].z; aw1 += v1 * m[k+1].w;
            }
            float ax = ax0 + ax1, ay = ay0 + ay1, az = az0 + az1, aw = aw0 + aw1;

            // 3. reduce over row classes: in-warp (g low bits) then cross-warp
            #pragma unroll
            for (int off = 4; off < 32; off <<= 1) {
                ax += __shfl_xor_sync(0xffffffffu, ax, off);
                ay += __shfl_xor_sync(0xffffffffu, ay, off);
                az += __shfl_xor_sync(0xffffffffu, az, off);
                aw += __shfl_xor_sync(0xffffffffu, aw, off);
            }
            if (lane < 4) {
                swp[wid][lane][0] = ax; swp[wid][lane][1] = ay;
                swp[wid][lane][2] = az; swp[wid][lane][3] = aw;
            }
            __syncthreads();
            if (tid < 16) {
                float s = 0.f;
                #pragma unroll
                for (int w = 0; w < 8; ++w) s += swp[w][tid >> 2][tid & 3];
                sdata[tid] = s;
            }
            __syncthreads();

            // 4. publish: tid0 stores its block's 16 outputs, then releases
            //    its flag (release orders tid0's own prior stores; no membar).
            if (tid == 0) {
                float4* dst = &g_V[t & 1][c0 >> 2];
                const float4* sd4 = reinterpret_cast<const float4*>(sdata);
                __stcg(&dst[0], sd4[0]); __stcg(&dst[1], sd4[1]);
                __stcg(&dst[2], sd4[2]); __stcg(&dst[3], sd4[3]);
                st_rel(&g_flag_f[b].x, base + (unsigned)t + 1u);
            }

            // 5. prefetch next matrix tile AFTER the release so the critical
            //    path never queues behind 512 L1tex wavefronts; it drains
            //    during the next inter-step wait.
            if (t + 1 < HALF) {
                const float4* M4 = reinterpret_cast<const float4*>(
                                       core + ((size_t)sx[t+1] << 20)) + (c0 >> 2) + j4;
                #pragma unroll
                for (int k = 0; k < 16; ++k) m[k] = __ldcg(&M4[(size_t)(g + 64*k) * 256]);
            }
        }
    } else {
        // ------- backward: w_i <- sum_j M[i][j] w_j; block owns rows [16gb,16gb+16) -------
        const int r0    = gb * 16;
        const int chunk = tid & 15;      // float4 chunk within the row
        const int row   = r0 + (tid >> 4);

        float4 m[16];
        {   // prefetch step 0
            const float4* M4 = reinterpret_cast<const float4*>(
                                   core + ((size_t)sx[0] << 20))
                               + (size_t)row * 256 + chunk;
            #pragma unroll
            for (int k = 0; k < 16; ++k) m[k] = __ldcg(&M4[16 * k]);
        }

        for (int t = 0; t < HALF; ++t) {
            if (t > 0) {
                if (wid == 0) warp_wait_all(g_flag_b, base + (unsigned)t);
                __syncthreads();
                reinterpret_cast<float4*>(sv)[tid] =
                    __ldcg(&g_W[(t + 1) & 1][tid]);
            } else {
                reinterpret_cast<float4*>(sv)[tid] =
                    reinterpret_cast<const float4*>(rb)[tid];
            }
            __syncthreads();

            float a0=0.f, a1=0.f, a2=0.f, a3=0.f;
            const float4* sw4 = reinterpret_cast<const float4*>(sv);
            #pragma unroll
            for (int k = 0; k < 16; ++k) {
                const float4 wv = sw4[chunk + 16*k];
                a0 += m[k].x * wv.x; a1 += m[k].y * wv.y;
                a2 += m[k].z * wv.z; a3 += m[k].w * wv.w;
            }
            float acc = (a0 + a1) + (a2 + a3);

            // reduce over chunk (lane bits 0..3)
            #pragma unroll
            for (int off = 1; off < 16; off <<= 1)
                acc += __shfl_xor_sync(0xffffffffu, acc, off);
            if (chunk == 0) sdata[tid >> 4] = acc;
            __syncthreads();

            if (tid == 0) {
                float4* dst = &g_W[t & 1][r0 >> 2];
                const float4* sd4 = reinterpret_cast<const float4*>(sdata);
                __stcg(&dst[0], sd4[0]); __stcg(&dst[1], sd4[1]);
                __stcg(&dst[2], sd4[2]); __stcg(&dst[3], sd4[3]);
                st_rel(&g_flag_b[gb].x, base + (unsigned)t + 1u);
            }

            if (t + 1 < HALF) {
                const float4* M4 = reinterpret_cast<const float4*>(
                                       core + ((size_t)sx[t+1] << 20))
                                   + (size_t)row * 256 + chunk;
                #pragma unroll
                for (int k = 0; k < 16; ++k) m[k] = __ldcg(&M4[16 * k]);
            }
        }
    }

    // ------- final combine: block 0 waits for both chains, dots v·w -------
    if (b == 0) {
        const unsigned thrF = base + (unsigned)HALF;
        if (wid == 0) {
            warp_wait_all(g_flag_f, thrF);
            warp_wait_all(g_flag_b, thrF);
        }
        __syncthreads();

        const float4 vv = __ldcg(&g_V[(HALF - 1) & 1][tid]);
        const float4 ww = __ldcg(&g_W[(HALF - 1) & 1][tid]);
        float part = vv.x*ww.x + vv.y*ww.y + vv.z*ww.z + vv.w*ww.w;
        #pragma unroll
        for (int off = 16; off > 0; off >>= 1)
            part += __shfl_xor_sync(0xffffffffu, part, off);
        if (lane == 0) sred[wid] = part;
        __syncthreads();
        if (tid == 0) {
            float s = 0.f;
            #pragma unroll
            for (int w = 0; w < 8; ++w) s += sred[w];
            out[0] = s;
        }
    }
}

extern "C" void kernel_launch(void* const* d_in, const int* in_sizes, int n_in,
                              void* d_out, int out_size) {
    const int*   x    = (const int*)  d_in[0];  // int32[1024]
    const float* core = (const float*)d_in[1];  // f32[32,1024,1024]
    const float* lb   = (const float*)d_in[2];  // f32[1024]
    const float* rb   = (const float*)d_in[3];  // f32[1024]
    float*       out  = (float*)d_out;

    tn_flag_kernel<<<NBLK, TPB>>>(x, core, lb, rb, out);
}

// round 9
// speedup vs baseline: 4.3453x; 1.2344x over previous
#include <cuda_runtime.h>
#include <cuda_fp16.h>
#include <cstdint>

#define FLEN 1024   // chain length
#define DDIM 1024   // bond dimension
#define HALF 512    // steps per direction
#define NGRP 64     // blocks per direction
#define NBLK (2*NGRP)
#define TPB  256
#define TILE_BYTES 32768            // 16 vectors x 1024 halves
// dynamic smem layout
#define SMEM_SV    (3*TILE_BYTES)           // float[1024]
#define SMEM_SX    (SMEM_SV + 4096)         // int[512]
#define SMEM_SD    (SMEM_SX + 2048)         // float[16]
#define SMEM_MBAR  (SMEM_SD + 64)           // 3 x u64
#define SMEM_TOTAL (SMEM_MBAR + 64)

// fp16 copies of core, built by a pre-pass every launch (idempotent).
// g_ct: column-major  [c][j][i]  -> forward reads 16 contiguous columns
// g_cr: row-major     [c][i][j]  -> backward reads 16 contiguous rows
__device__ __align__(128) __half g_ct[(size_t)32*1024*1024];
__device__ __align__(128) __half g_cr[(size_t)32*1024*1024];

// Chain vectors (fp32) + per-block epoch flags. Flags grow monotonically
// across graph replays; all 128 flags are equal at every launch boundary.
__device__ float4 g_V[2][DDIM/4];
__device__ float4 g_W[2][DDIM/4];
__device__ uint4  g_flag_f[NGRP];
__device__ uint4  g_flag_b[NGRP];

// ---------------- helpers ----------------
__device__ __forceinline__ unsigned ld_acq(const unsigned* p) {
    unsigned v;
    asm volatile("ld.acquire.gpu.u32 %0, [%1];" : "=r"(v) : "l"(p) : "memory");
    return v;
}
__device__ __forceinline__ void st_rel(unsigned* p, unsigned v) {
    asm volatile("st.release.gpu.u32 [%0], %1;" :: "l"(p), "r"(v) : "memory");
}
__device__ __forceinline__ unsigned smem_u32(const void* p) {
    unsigned a;
    asm("{ .reg .u64 t; cvta.to.shared.u64 t, %1; cvt.u32.u64 %0, t; }"
        : "=r"(a) : "l"(p));
    return a;
}
__device__ __forceinline__ void mbar_init(unsigned a, unsigned cnt) {
    asm volatile("mbarrier.init.shared.b64 [%0], %1;" :: "r"(a), "r"(cnt) : "memory");
}
__device__ __forceinline__ void mbar_expect(unsigned a, unsigned tx) {
    asm volatile("mbarrier.arrive.expect_tx.shared.b64 _, [%0], %1;"
                 :: "r"(a), "r"(tx) : "memory");
}
__device__ __forceinline__ void bulk_g2s(unsigned dst, const void* src,
                                         unsigned bytes, unsigned mbar) {
    asm volatile("cp.async.bulk.shared::cluster.global.mbarrier::complete_tx::bytes "
                 "[%0], [%1], %2, [%3];"
                 :: "r"(dst), "l"(src), "r"(bytes), "r"(mbar) : "memory");
}
__device__ __forceinline__ void mbar_wait(unsigned a, unsigned ph) {
    unsigned done;
    asm volatile("{ .reg .pred p; "
                 "mbarrier.try_wait.parity.acquire.cta.shared::cta.b64 p, [%1], %2; "
                 "selp.b32 %0, 1, 0, p; }"
                 : "=r"(done) : "r"(a), "r"(ph) : "memory");
    if (!done) {
        asm volatile("{ .reg .pred P1; "
                     "W%=: mbarrier.try_wait.parity.acquire.cta.shared::cta.b64 P1, [%0], %1, 0x989680; "
                     "@P1 bra D%=; bra W%=; D%=: }"
                     :: "r"(a), "r"(ph) : "memory");
    }
}
// One warp polls all 64 flags until every epoch >= thr (coalesced, 2 loads/lane).
__device__ __forceinline__ void warp_wait_all(const uint4* fl, unsigned thr) {
    const int lane = threadIdx.x & 31;
    unsigned ok;
    do {
        const unsigned f0 = ld_acq(&fl[lane].x);
        const unsigned f1 = ld_acq(&fl[lane + 32].x);
        ok = ((int)(f0 - thr) >= 0) && ((int)(f1 - thr) >= 0);
    } while (!__all_sync(0xffffffffu, ok));
}

// ---------------- pre-pass: fp32 -> fp16 in two layouts ----------------
// grid = 32 matrices x 16 x 16 tiles of 64x64; block = 256 threads.
__global__ void __launch_bounds__(256, 2)
convert_kernel(const float* __restrict__ core)
{
    __shared__ float s[64][65];
    const int tile = blockIdx.x;
    const int c  = tile >> 8;
    const int i0 = ((tile >> 4) & 15) << 6;
    const int j0 = (tile & 15) << 6;
    const int tid = threadIdx.x;
    const float* src = core + ((size_t)c << 20);

    #pragma unroll
    for (int p = 0; p < 4; ++p) {          // load 64x64 fp32 + write row-major fp16
        const int fid = tid + (p << 8);
        const int row = fid >> 4, col4 = fid & 15;
        const float4 v = *reinterpret_cast<const float4*>(
            src + ((size_t)(i0 + row) << 10) + j0 + (col4 << 2));
        __half2 h0 = __floats2half2_rn(v.x, v.y);
        __half2 h1 = __floats2half2_rn(v.z, v.w);
        uint2 u = make_uint2(*reinterpret_cast<unsigned*>(&h0),
                             *reinterpret_cast<unsigned*>(&h1));
        *reinterpret_cast<uint2*>(
            &g_cr[(((size_t)c << 10) + (i0 + row)) * 1024 + j0 + (col4 << 2)]) = u;
        s[row][(col4 << 2) + 0] = v.x; s[row][(col4 << 2) + 1] = v.y;
        s[row][(col4 << 2) + 2] = v.z; s[row][(col4 << 2) + 3] = v.w;
    }
    __syncthreads();
    #pragma unroll
    for (int p = 0; p < 4; ++p) {          // write transposed (column-major) fp16
        const int id = tid + (p << 8);
        const int jr = id >> 4, i4 = id & 15;
        __half2 h0 = __floats2half2_rn(s[(i4 << 2) + 0][jr], s[(i4 << 2) + 1][jr]);
        __half2 h1 = __floats2half2_rn(s[(i4 << 2) + 2][jr], s[(i4 << 2) + 3][jr]);
        uint2 u = make_uint2(*reinterpret_cast<unsigned*>(&h0),
                             *reinterpret_cast<unsigned*>(&h1));
        *reinterpret_cast<uint2*>(
            &g_ct[(((size_t)c << 10) + (j0 + jr)) * 1024 + i0 + (i4 << 2)]) = u;
    }
}

// ---------------- persistent chain kernel ----------------
__global__ void __launch_bounds__(TPB, 1)
tn_tma_kernel(const int*   __restrict__ x,
              const float* __restrict__ lb,
              const float* __restrict__ rb,
              float*       __restrict__ out)
{
    extern __shared__ char smem[];
    float* sv    = reinterpret_cast<float*>(smem + SMEM_SV);
    int*   sx    = reinterpret_cast<int*>  (smem + SMEM_SX);
    float* sdata = reinterpret_cast<float*>(smem + SMEM_SD);
    const unsigned sbase = smem_u32(smem);
    const unsigned mb0   = sbase + SMEM_MBAR;

    const int tid  = threadIdx.x;
    const int b    = blockIdx.x;
    const int lane = tid & 31;
    const int wid  = tid >> 5;
    const bool fwd = (b < NGRP);
    const int  gb  = fwd ? b : b - NGRP;

    uint4*        flg   = fwd ? g_flag_f : g_flag_b;
    const __half* mat   = fwd ? g_ct : g_cr;     // contiguous stripes either way
    float4 (*vio)[DDIM/4] = fwd ? g_V : g_W;
    const float*  bound = fwd ? lb : rb;

    // Common launch base (all 128 flags equal at every launch boundary).
    const unsigned base = ld_acq(&flg[gb].x);

    if (tid == 0) {
        mbar_init(mb0, 1); mbar_init(mb0 + 8, 1); mbar_init(mb0 + 16, 1);
        asm volatile("fence.proxy.async.shared::cta;" ::: "memory");
    }
    if (fwd) { for (int t = tid; t < HALF; t += TPB) sx[t] = x[t]; }
    else     { for (int t = tid; t < HALF; t += TPB) sx[t] = x[FLEN - 1 - t]; }
    __syncthreads();

    const size_t stripe = (size_t)(gb * 16) << 10;   // 16K halves per block
    if (tid == 0) {   // prime 2 tiles of the 3-deep ring
        mbar_expect(mb0, TILE_BYTES);
        bulk_g2s(sbase, mat + (((size_t)sx[0]) << 20) + stripe, TILE_BYTES, mb0);
        mbar_expect(mb0 + 8, TILE_BYTES);
        bulk_g2s(sbase + TILE_BYTES, mat + (((size_t)sx[1]) << 20) + stripe,
                 TILE_BYTES, mb0 + 8);
    }

    const int q0 = wid << 1;   // each warp owns 2 of the 16 output elements

    for (int t = 0; t < HALF; ++t) {
        // 1. rendezvous + fetch chain vector (LSU is quiet: no LDG stream here)
        if (t > 0) {
            if (wid == 0) warp_wait_all(flg, base + (unsigned)t);
            __syncthreads();
            reinterpret_cast<float4*>(sv)[tid] = __ldcg(&vio[(t + 1) & 1][tid]);
        } else {
            reinterpret_cast<float4*>(sv)[tid] =
                reinterpret_cast<const float4*>(bound)[tid];
        }
        __syncthreads();

        // 2. wait this step's TMA tile (issued >= 2 steps ago; normally done)
        const int slot = t % 3;
        mbar_wait(mb0 + slot * 8, (unsigned)((t / 3) & 1));

        // 3. dot 2 contiguous fp16 vectors against sv (fp32 accumulate)
        const __half* tile = reinterpret_cast<const __half*>(smem + slot * TILE_BYTES);
        const uint4* t0 = reinterpret_cast<const uint4*>(tile + (q0 << 10));
        const uint4* t1 = reinterpret_cast<const uint4*>(tile + ((q0 + 1) << 10));
        const float4* sv4 = reinterpret_cast<const float4*>(sv);
        float acc0 = 0.f, acc1 = 0.f;
        #pragma unroll
        for (int k = 0; k < 4; ++k) {
            const int idx = lane + (k << 5);
            const uint4 m0 = t0[idx];
            const uint4 m1 = t1[idx];
            const float4 va = sv4[idx << 1];
            const float4 vb = sv4[(idx << 1) + 1];
            float2 f;
            f = __half22float2(*reinterpret_cast<const __half2*>(&m0.x)); acc0 += f.x*va.x + f.y*va.y;
            f = __half22float2(*reinterpret_cast<const __half2*>(&m0.y)); acc0 += f.x*va.z + f.y*va.w;
            f = __half22float2(*reinterpret_cast<const __half2*>(&m0.z)); acc0 += f.x*vb.x + f.y*vb.y;
            f = __half22float2(*reinterpret_cast<const __half2*>(&m0.w)); acc0 += f.x*vb.z + f.y*vb.w;
            f = __half22float2(*reinterpret_cast<const __half2*>(&m1.x)); acc1 += f.x*va.x + f.y*va.y;
            f = __half22float2(*reinterpret_cast<const __half2*>(&m1.y)); acc1 += f.x*va.z + f.y*va.w;
            f = __half22float2(*reinterpret_cast<const __half2*>(&m1.z)); acc1 += f.x*vb.x + f.y*vb.y;
            f = __half22float2(*reinterpret_cast<const __half2*>(&m1.w)); acc1 += f.x*vb.z + f.y*vb.w;
        }
        #pragma unroll
        for (int off = 16; off > 0; off >>= 1) {
            acc0 += __shfl_xor_sync(0xffffffffu, acc0, off);
            acc1 += __shfl_xor_sync(0xffffffffu, acc1, off);
        }
        if (lane == 0) { sdata[q0] = acc0; sdata[q0 + 1] = acc1; }
        __syncthreads();

        // 4. publish 16 outputs + release flag; then queue tile t+2
        if (tid == 0) {
            float4* dst = &vio[t & 1][gb << 2];
            const float4* sd = reinterpret_cast<const float4*>(sdata);
            __stcg(&dst[0], sd[0]); __stcg(&dst[1], sd[1]);
            __stcg(&dst[2], sd[2]); __stcg(&dst[3], sd[3]);
            st_rel(&flg[gb].x, base + (unsigned)t + 1u);
            if (t + 2 < HALF) {
                const int s2 = (t + 2) % 3;
                mbar_expect(mb0 + s2 * 8, TILE_BYTES);
                bulk_g2s(sbase + s2 * TILE_BYTES,
                         mat + (((size_t)sx[t + 2]) << 20) + stripe,
                         TILE_BYTES, mb0 + s2 * 8);
            }
        }
    }

    // ---- final combine: block 0 waits for both chains, dots v . w ----
    if (b == 0) {
        const unsigned thrF = base + (unsigned)HALF;
        if (wid == 0) {
            warp_wait_all(g_flag_f, thrF);
            warp_wait_all(g_flag_b, thrF);
        }
        __syncthreads();
        const float4 vv = __ldcg(&g_V[(HALF - 1) & 1][tid]);
        const float4 ww = __ldcg(&g_W[(HALF - 1) & 1][tid]);
        float part = vv.x*ww.x + vv.y*ww.y + vv.z*ww.z + vv.w*ww.w;
        #pragma unroll
        for (int off = 16; off > 0; off >>= 1)
            part += __shfl_xor_sync(0xffffffffu, part, off);
        if (lane == 0) sdata[wid] = part;
        __syncthreads();
        if (tid == 0) {
            float s = 0.f;
            #pragma unroll
            for (int w = 0; w < 8; ++w) s += sdata[w];
            out[0] = s;
        }
    }
}

extern "C" void kernel_launch(void* const* d_in, const int* in_sizes, int n_in,
                              void* d_out, int out_size) {
    const int*   x    = (const int*)  d_in[0];  // int32[1024]
    const float* core = (const float*)d_in[1];  // f32[32,1024,1024]
    const float* lb   = (const float*)d_in[2];  // f32[1024]
    const float* rb   = (const float*)d_in[3];  // f32[1024]
    float*       out  = (float*)d_out;

    // idempotent + deterministic per call (no static guards)
    cudaFuncSetAttribute(tn_tma_kernel,
                         cudaFuncAttributeMaxDynamicSharedMemorySize, SMEM_TOTAL);
    convert_kernel<<<32 * 16 * 16, 256>>>(core);
    tn_tma_kernel<<<NBLK, TPB, SMEM_TOTAL>>>(x, lb, rb, out);
}

// round 11
// speedup vs baseline: 6.5718x; 1.5124x over previous
#include <cuda_runtime.h>
#include <cuda_fp16.h>
#include <cstdint>

#define FLEN 1024
#define DDIM 1024
#define HALF 512            // steps per direction
#define NGRP 32             // blocks per direction
#define NBLK (2*NGRP)
#define TPB  512
#define NRB  8              // chain-vector ring depth
#define TILE_BYTES 65536    // 32 vectors x 1024 halves x 2B
#define SENT 0x7FA00BADu    // qNaN payload; chain data is strictly positive

// dynamic smem layout
#define SMEM_SV    (3*TILE_BYTES)           // float[1024]
#define SMEM_SX    (SMEM_SV + 4096)         // int[512]
#define SMEM_SP    (SMEM_SX + 2048)         // float[16][32] partials
#define SMEM_MBAR  (SMEM_SP + 2048)
#define SMEM_TOTAL (SMEM_MBAR + 64)

// fp16 copies of core (built each launch; idempotent).
// g_ct: column-major (forward reads 32 contiguous columns)
// g_cr: row-major    (backward reads 32 contiguous rows)
__device__ __align__(128) __half g_ct[(size_t)32*1024*1024];
__device__ __align__(128) __half g_cr[(size_t)32*1024*1024];

// Self-validating chain-vector rings. SCALAR 4-byte records only: naturally
// aligned 4B accesses are single-transaction (the R10 float2 records were not
// guaranteed to be, and could be observed half-written).
__device__ __align__(16) float g_rsV[NRB][DDIM];
__device__ __align__(16) float g_rsW[NRB][DDIM];

// ---------------- helpers ----------------
__device__ __forceinline__ float ld_vol_f32(const float* p) {
    float v;
    asm volatile("ld.volatile.global.f32 %0, [%1];" : "=f"(v) : "l"(p) : "memory");
    return v;
}
__device__ __forceinline__ void st_vol_f32(float* p, float v) {
    asm volatile("st.volatile.global.f32 [%0], %1;" :: "l"(p), "f"(v) : "memory");
}
__device__ __forceinline__ unsigned smem_u32(const void* p) {
    unsigned a;
    asm("{ .reg .u64 t; cvta.to.shared.u64 t, %1; cvt.u32.u64 %0, t; }"
        : "=r"(a) : "l"(p));
    return a;
}
__device__ __forceinline__ void mbar_init(unsigned a, unsigned cnt) {
    asm volatile("mbarrier.init.shared.b64 [%0], %1;" :: "r"(a), "r"(cnt) : "memory");
}
__device__ __forceinline__ void mbar_expect(unsigned a, unsigned tx) {
    asm volatile("mbarrier.arrive.expect_tx.shared.b64 _, [%0], %1;"
                 :: "r"(a), "r"(tx) : "memory");
}
__device__ __forceinline__ void bulk_g2s(unsigned dst, const void* src,
                                         unsigned bytes, unsigned mbar) {
    asm volatile("cp.async.bulk.shared::cluster.global.mbarrier::complete_tx::bytes "
                 "[%0], [%1], %2, [%3];"
                 :: "r"(dst), "l"(src), "r"(bytes), "r"(mbar) : "memory");
}
__device__ __forceinline__ void mbar_wait(unsigned a, unsigned ph) {
    unsigned done;
    asm volatile("{ .reg .pred p; "
                 "mbarrier.try_wait.parity.acquire.cta.shared::cta.b64 p, [%1], %2; "
                 "selp.b32 %0, 1, 0, p; }"
                 : "=r"(done) : "r"(a), "r"(ph) : "memory");
    if (!done) {
        asm volatile("{ .reg .pred P1; "
                     "W%=: mbarrier.try_wait.parity.acquire.cta.shared::cta.b64 P1, [%0], %1, 0x989680; "
                     "@P1 bra D%=; bra W%=; D%=: }"
                     :: "r"(a), "r"(ph) : "memory");
    }
}

// ---------------- init: sentinel-fill both rings (every launch) ----------------
__global__ void init_kernel() {
    const unsigned tid = blockIdx.x * blockDim.x + threadIdx.x;
    const float s = __uint_as_float(SENT);
    for (unsigned i = tid; i < NRB * DDIM; i += gridDim.x * blockDim.x) {
        st_vol_f32(&g_rsV[0][0] + i, s);
        st_vol_f32(&g_rsW[0][0] + i, s);
    }
}

// ---------------- pre-pass: fp32 -> fp16 in two layouts ----------------
__global__ void __launch_bounds__(256, 2)
convert_kernel(const float* __restrict__ core)
{
    __shared__ float s[64][65];
    const int tile = blockIdx.x;
    const int c  = tile >> 8;
    const int i0 = ((tile >> 4) & 15) << 6;
    const int j0 = (tile & 15) << 6;
    const int tid = threadIdx.x;
    const float* src = core + ((size_t)c << 20);

    #pragma unroll
    for (int p = 0; p < 4; ++p) {
        const int fid = tid + (p << 8);
        const int row = fid >> 4, col4 = fid & 15;
        const float4 v = *reinterpret_cast<const float4*>(
            src + ((size_t)(i0 + row) << 10) + j0 + (col4 << 2));
        __half2 h0 = __floats2half2_rn(v.x, v.y);
        __half2 h1 = __floats2half2_rn(v.z, v.w);
        uint2 u = make_uint2(*reinterpret_cast<unsigned*>(&h0),
                             *reinterpret_cast<unsigned*>(&h1));
        *reinterpret_cast<uint2*>(
            &g_cr[(((size_t)c << 10) + (i0 + row)) * 1024 + j0 + (col4 << 2)]) = u;
        s[row][(col4 << 2) + 0] = v.x; s[row][(col4 << 2) + 1] = v.y;
        s[row][(col4 << 2) + 2] = v.z; s[row][(col4 << 2) + 3] = v.w;
    }
    __syncthreads();
    #pragma unroll
    for (int p = 0; p < 4; ++p) {
        const int id = tid + (p << 8);
        const int jr = id >> 4, i4 = id & 15;
        __half2 h0 = __floats2half2_rn(s[(i4 << 2) + 0][jr], s[(i4 << 2) + 1][jr]);
        __half2 h1 = __floats2half2_rn(s[(i4 << 2) + 2][jr], s[(i4 << 2) + 3][jr]);
        uint2 u = make_uint2(*reinterpret_cast<unsigned*>(&h0),
                             *reinterpret_cast<unsigned*>(&h1));
        *reinterpret_cast<uint2*>(
            &g_ct[(((size_t)c << 10) + (j0 + jr)) * 1024 + i0 + (i4 << 2)]) = u;
    }
}

// ---------------- persistent chain kernel ----------------
__global__ void __launch_bounds__(TPB, 1)
tn_sentinel_kernel(const int*   __restrict__ x,
                   const float* __restrict__ lb,
                   const float* __restrict__ rb,
                   float*       __restrict__ out)
{
    extern __shared__ char smem[];
    float* sv    = reinterpret_cast<float*>(smem + SMEM_SV);
    int*   sx    = reinterpret_cast<int*>  (smem + SMEM_SX);
    float* spart = reinterpret_cast<float*>(smem + SMEM_SP);
    const unsigned sbase = smem_u32(smem);
    const unsigned mb0   = sbase + SMEM_MBAR;

    const int tid = threadIdx.x;
    const int b   = blockIdx.x;
    const int l   = tid & 31;
    const int w   = tid >> 5;      // 16 warps
    const int g   = l >> 3;        // column group 0..3
    const int r   = l & 7;         // i-subrange within warp segment
    const bool fwd = (b < NGRP);
    const int  ob  = fwd ? b : b - NGRP;

    const __half* mat = fwd ? g_ct : g_cr;
    float (*ring)[DDIM] = fwd ? g_rsV : g_rsW;
    const float* bound = fwd ? lb : rb;

    if (tid == 0) {
        mbar_init(mb0, 1); mbar_init(mb0 + 8, 1); mbar_init(mb0 + 16, 1);
        asm volatile("fence.proxy.async.shared::cta;" ::: "memory");
    }
    if (fwd) { for (int t = tid; t < HALF; t += TPB) sx[t] = x[t]; }
    else     { for (int t = tid; t < HALF; t += TPB) sx[t] = x[FLEN - 1 - t]; }
    __syncthreads();

    const size_t stripe = (size_t)ob << 15;   // 32*1024 halves per block
    if (tid == 0) {   // prime tiles for steps 0 and 1
        mbar_expect(mb0, TILE_BYTES);
        bulk_g2s(sbase, mat + (((size_t)sx[0]) << 20) + stripe, TILE_BYTES, mb0);
        mbar_expect(mb0 + 8, TILE_BYTES);
        bulk_g2s(sbase + TILE_BYTES, mat + (((size_t)sx[1]) << 20) + stripe,
                 TILE_BYTES, mb0 + 8);
    }

    const float sentf = __uint_as_float(SENT);

    for (int t = 0; t < HALF; ++t) {
        // 1. this step's tile must be resident (TMA issued >= 2 steps ago)
        const int slot = t % 3;
        mbar_wait(mb0 + slot * 8, (unsigned)((t / 3) & 1));

        // 2. prefetch matrix quads into regs (crossbar cost hides under wait)
        const char* tile = smem + slot * TILE_BYTES;
        uint4 m[8];
        #pragma unroll
        for (int k = 0; k < 8; ++k) {
            const int c = (k << 2) + g;              // vector index 0..31
            m[k] = *reinterpret_cast<const uint4*>(
                tile + c * 2048 + ((w << 3) + r) * 16);
        }

        // 3. queue TMA for step t+2 (slot (t+2)%3 was consumed at step t-1)
        if (tid == 0 && t + 2 < HALF) {
            const int s2 = (t + 2) % 3;
            mbar_expect(mb0 + s2 * 8, TILE_BYTES);
            bulk_g2s(sbase + s2 * TILE_BYTES,
                     mat + (((size_t)sx[t + 2]) << 20) + stripe, TILE_BYTES,
                     mb0 + s2 * 8);
        }

        // 4. obtain chain vector: each thread polls TWO scalar 4B records
        //    (naturally-aligned 4B accesses are single-transaction)
        float2 myv;
        if (t == 0) {
            myv = reinterpret_cast<const float2*>(bound)[tid];
        } else {
            const float* src = &ring[(t - 1) & 7][tid << 1];
            do { myv.x = ld_vol_f32(src); }
            while (__float_as_uint(myv.x) == SENT);
            do { myv.y = ld_vol_f32(src + 1); }
            while (__float_as_uint(myv.y) == SENT);
        }
        reinterpret_cast<float2*>(sv)[tid] = myv;
        __syncthreads();

        // 5. compute: warp w covers terms i in [64w, 64w+64) of ALL 32 vectors
        const float4* sf4 = reinterpret_cast<const float4*>(sv);
        const float4 va = sf4[(w << 4) + (r << 1)];
        const float4 vb = sf4[(w << 4) + (r << 1) + 1];
        float acc[8];
        #pragma unroll
        for (int k = 0; k < 8; ++k) {
            float2 f; float s = 0.f;
            f = __half22float2(*reinterpret_cast<const __half2*>(&m[k].x));
            s = fmaf(f.x, va.x, s); s = fmaf(f.y, va.y, s);
            f = __half22float2(*reinterpret_cast<const __half2*>(&m[k].y));
            s = fmaf(f.x, va.z, s); s = fmaf(f.y, va.w, s);
            f = __half22float2(*reinterpret_cast<const __half2*>(&m[k].z));
            s = fmaf(f.x, vb.x, s); s = fmaf(f.y, vb.y, s);
            f = __half22float2(*reinterpret_cast<const __half2*>(&m[k].w));
            s = fmaf(f.x, vb.z, s); s = fmaf(f.y, vb.w, s);
            acc[k] = s;
        }
        #pragma unroll
        for (int k = 0; k < 8; ++k) {
            #pragma unroll
            for (int off = 1; off < 8; off <<= 1)
                acc[k] += __shfl_xor_sync(0xffffffffu, acc[k], off);
        }
        if (r == 0) {
            #pragma unroll
            for (int k = 0; k < 8; ++k) spart[(w << 5) + (k << 2) + g] = acc[k];
        }
        __syncthreads();

        // 6. warp 0: cross-warp reduce + publish 32 scalar records (each
        //    self-validating, single 4B transaction) + re-sentinel slot t+4
        //    (its data is >= 2 steps consumed under the lag<=1 invariant;
        //    same-thread same-address ordering keeps clear before next write)
        if (tid < 32) {
            float s = 0.f;
            #pragma unroll
            for (int w2 = 0; w2 < 16; ++w2) s += spart[(w2 << 5) + tid];
            const int e = (ob << 5) + tid;
            st_vol_f32(&ring[t & 7][e], s);
            st_vol_f32(&ring[(t + 4) & 7][e], sentf);
        }
    }

    // ---- final combine: block 0 polls both final vectors, dots them ----
    if (b == 0) {
        const float* pv = &g_rsV[(HALF - 1) & 7][tid << 1];
        const float* pw = &g_rsW[(HALF - 1) & 7][tid << 1];
        float2 vf, wf;
        do { vf.x = ld_vol_f32(pv);     } while (__float_as_uint(vf.x) == SENT);
        do { vf.y = ld_vol_f32(pv + 1); } while (__float_as_uint(vf.y) == SENT);
        do { wf.x = ld_vol_f32(pw);     } while (__float_as_uint(wf.x) == SENT);
        do { wf.y = ld_vol_f32(pw + 1); } while (__float_as_uint(wf.y) == SENT);
        float part = vf.x * wf.x + vf.y * wf.y;
        #pragma unroll
        for (int off = 16; off > 0; off >>= 1)
            part += __shfl_xor_sync(0xffffffffu, part, off);
        if (l == 0) spart[w] = part;
        __syncthreads();
        if (tid == 0) {
            float s = 0.f;
            #pragma unroll
            for (int w2 = 0; w2 < 16; ++w2) s += spart[w2];
            out[0] = s;
        }
    }
}

extern "C" void kernel_launch(void* const* d_in, const int* in_sizes, int n_in,
                              void* d_out, int out_size) {
    const int*   x    = (const int*)  d_in[0];  // int32[1024]
    const float* core = (const float*)d_in[1];  // f32[32,1024,1024]
    const float* lb   = (const float*)d_in[2];  // f32[1024]
    const float* rb   = (const float*)d_in[3];  // f32[1024]
    float*       out  = (float*)d_out;

    cudaFuncSetAttribute(tn_sentinel_kernel,
                         cudaFuncAttributeMaxDynamicSharedMemorySize, SMEM_TOTAL);
    init_kernel<<<16, 512>>>();
    convert_kernel<<<32 * 16 * 16, 256>>>(core);
    tn_sentinel_kernel<<<NBLK, TPB, SMEM_TOTAL>>>(x, lb, rb, out);
}